// round 15
// baseline (speedup 1.0000x reference)
#include <cuda_runtime.h>
#include <math.h>

#define P       512
#define K_MAX   16
#define NM      (K_MAX + 1)
#define M_CAP   65536
#define NCH_MAX 256
#define NB      64
#define NSTEP   (P / NB)      // 8
#define NSLICE  3
#define DP      68
#define NCTA    15
#define REG     4352          // smem region stride (floats)

#define FT_SMEM_BYTES (4 * REG * 4)   // 69632 B

typedef unsigned long long ull;

// ---------------- f32x2 packed helpers (Blackwell sm_103a) -----------------
__device__ __forceinline__ ull ffma2(ull a, ull b, ull c) {
    ull d;
    asm("fma.rn.f32x2 %0, %1, %2, %3;" : "=l"(d) : "l"(a), "l"(b), "l"(c));
    return d;
}
__device__ __forceinline__ ull dup2(float x) {
    ull r; unsigned xb = __float_as_uint(x);
    asm("mov.b64 %0, {%1, %2};" : "=l"(r) : "r"(xb), "r"(xb));
    return r;
}
__device__ __forceinline__ ull pack2(float lo, float hi) {
    ull r;
    asm("mov.b64 %0, {%1, %2};" : "=l"(r) : "f"(lo), "f"(hi));
    return r;
}
__device__ __forceinline__ float2 unpk2(ull v) {
    float2 r;
    asm("mov.b64 {%0, %1}, %2;" : "=f"(r.x), "=f"(r.y) : "l"(v));
    return r;
}

// ---------------- device scratch -------------------------------------------
__device__ int    d_cnt[K_MAX];
__device__ int    d_kval;
__device__ int    d_idx[M_CAP];
__device__ int    d_bh[NCH_MAX][K_MAX];
__device__ int    d_boff[NCH_MAX][K_MAX];
__device__ int    d_cstart[K_MAX];
__device__ int    d_lbar;
__device__ int    d_done;
__device__ int    d_zflag[NM];
__device__ int    d_wflag[NM][NSTEP - 1];
__device__ int    d_tflag[NM][64];
__device__ float  d_Gk[NSLICE][K_MAX][P * P];
__device__ float  d_A[NM][P * P];
__device__ float  d_Z[NSTEP][NM][NB * 65];
__device__ float  d_W[NSTEP - 1][NM][NSTEP - 1][NB * DP];
__device__ double d_hldd[NM];

// ---------------- release/acquire primitives -------------------------------
__device__ __forceinline__ void rel_add(int* p) {
    int d;
    asm volatile("atom.release.gpu.add.s32 %0, [%1], 1;"
                 : "=r"(d) : "l"(p) : "memory");
}
__device__ __forceinline__ void rel_st(int* p, int v) {
    asm volatile("st.release.gpu.s32 [%0], %1;" :: "l"(p), "r"(v) : "memory");
}
__device__ __forceinline__ int acq_ld(const int* p) {
    int v;
    asm volatile("ld.acquire.gpu.s32 %0, [%1];" : "=r"(v) : "l"(p) : "memory");
    return v;
}
__device__ __forceinline__ void gbar(int nb, int ep) {
    __syncthreads();
    if (threadIdx.x == 0) {
        rel_add(&d_lbar);
        while (acq_ld(&d_lbar) < nb * ep) { }
    }
    __syncthreads();
}
__device__ __forceinline__ void fwait3(const int* p0, int v0,
                                       const int* p1, int v1,
                                       const int* p2, int v2) {
    if (threadIdx.x == 0) {
        if (p0) while (acq_ld(p0) < v0) { }
        if (p1) while (acq_ld(p1) < v1) { }
        if (p2) while (acq_ld(p2) < v2) { }
    }
    __syncthreads();
}

// ------- k_labels: dtype detect + hist + scan + stable scatter -------------
__global__ __launch_bounds__(256) void k_labels(const void* __restrict__ Y,
                                                const int* ncls, int m,
                                                int nchunk) {
    __shared__ int sh[K_MAX];
    __shared__ int swh[8 * K_MAX];
    __shared__ int nzf;
    int tid = threadIdx.x;
    int b = blockIdx.x;
    if (tid == 0) nzf = 0;
    if (tid < K_MAX) sh[tid] = 0;
    __syncthreads();

    int lim = m / 2; if (lim > 512) lim = 512;
    int found = 0;
    for (int i = tid; i < lim; i += 256)
        if (((const int*)Y)[2 * i + 1] != 0) found = 1;
    if (__any_sync(0xffffffffu, found)) {
        if ((tid & 31) == 0) atomicOr(&nzf, 1);
    }
    __syncthreads();
    int is64 = nzf ? 0 : 1;

    int i = b * 256 + tid;
    int c = -1;
    if (i < m) {
        c = is64 ? (int)((const long long*)Y)[i] : ((const int*)Y)[i];
        if (c < 0 || c >= K_MAX) c = 0;
        atomicAdd(&sh[c], 1);
    }
    __syncthreads();
    if (tid < K_MAX) d_bh[b][tid] = sh[tid];

    gbar(nchunk, 1);

    if (b == 0) {
        if (tid < K_MAX) {
            int run = 0;
            for (int bb = 0; bb < nchunk; bb++) {
                d_boff[bb][tid] = run;
                run += d_bh[bb][tid];
            }
            d_cnt[tid] = run;
            sh[tid] = run;
        }
        __syncthreads();
        if (tid == 0) {
            int run = 0;
            for (int cc = 0; cc < K_MAX; cc++) {
                d_cstart[cc] = run;
                run += sh[cc];
            }
            int k = ncls ? *ncls : 10;
            if (k < 1) k = 1;
            if (k > K_MAX) k = K_MAX;
            d_kval = k;
            d_done = 0;
        }
        if (tid < NM) { d_hldd[tid] = 0.0; d_zflag[tid] = 0; }
        for (int q = tid; q < NM * (NSTEP - 1); q += 256)
            ((int*)d_wflag)[q] = 0;
        for (int q = tid; q < NM * 64; q += 256)
            ((int*)d_tflag)[q] = 0;
    }

    gbar(nchunk, 2);

    if (tid < 8 * K_MAX) swh[tid] = 0;
    __syncthreads();
    int lane = tid & 31, w = tid >> 5;
    unsigned mask = __match_any_sync(0xffffffffu, c);
    int rin = __popc(mask & ((1u << lane) - 1u));
    int leader = __ffs(mask) - 1;
    if (c >= 0 && lane == leader) swh[w * K_MAX + c] = __popc(mask);
    __syncthreads();
    if (c >= 0) {
        int pre = 0;
        for (int w2 = 0; w2 < w; w2++) pre += swh[w2 * K_MAX + c];
        d_idx[d_cstart[c] + d_boff[b][c] + pre + rin] = i;
    }
}

// ------- per-class Gram: dense gather over sorted class range --------------
__global__ __launch_bounds__(256) void k_gram(const float* __restrict__ X,
                                              int p) {
    int c = blockIdx.y;
    if (c >= d_kval) return;
    int tile = blockIdx.x;
    int ti = 0;
    while ((ti + 1) * (ti + 2) / 2 <= tile) ti++;
    int tj = tile - ti * (ti + 1) / 2;
    int a0 = ti * 128, b0 = tj * 128;
    int z = blockIdx.z;
    int cstart = d_cstart[c], ccnt = d_cnt[c];
    int sb = (int)((long long)ccnt * z / NSLICE);
    int se = (int)((long long)ccnt * (z + 1) / NSLICE);

    __shared__ __align__(16) float sA[32][132];
    __shared__ __align__(16) float sB[32][132];
    __shared__ int sidx[32];

    int tid = threadIdx.x;
    int tx = tid & 15, ty = tid >> 4;
    int lt = tid >> 3, lc = tid & 7;

    ull acc2[8][4];
#pragma unroll
    for (int i = 0; i < 8; i++)
#pragma unroll
        for (int q = 0; q < 4; q++) acc2[i][q] = 0ull;

    for (int base = sb; base < se; base += 32) {
        int nv = se - base;
        if (nv > 32) nv = 32;
        __syncthreads();
        if (tid < 32)
            sidx[tid] = (tid < nv) ? d_idx[cstart + base + tid] : -1;
        __syncthreads();
        {
            int s = sidx[lt];
            if (s >= 0) {
                const float* xr = X + (size_t)s * p;
#pragma unroll
                for (int q = 0; q < 4; q++) {
                    int col = lc * 16 + q * 4;
                    *(float4*)&sA[lt][col] = *(const float4*)&xr[a0 + col];
                    *(float4*)&sB[lt][col] = *(const float4*)&xr[b0 + col];
                }
            }
        }
        __syncthreads();

        for (int t = 0; t < nv; t++) {
            float a[8];
            ull ad[8], b2[4];
            *(float4*)&a[0] = *(const float4*)&sA[t][ty * 8];
            *(float4*)&a[4] = *(const float4*)&sA[t][ty * 8 + 4];
#pragma unroll
            for (int i = 0; i < 8; i++) ad[i] = dup2(a[i]);
#pragma unroll
            for (int q = 0; q < 4; q++)
                b2[q] = *(const ull*)&sB[t][tx * 2 + q * 32];
#pragma unroll
            for (int i = 0; i < 8; i++)
#pragma unroll
                for (int q = 0; q < 4; q++)
                    acc2[i][q] = ffma2(ad[i], b2[q], acc2[i][q]);
        }
    }

    float* G = d_Gk[z][c];
    int gi = a0 + ty * 8;
#pragma unroll
    for (int i = 0; i < 8; i++)
#pragma unroll
        for (int q = 0; q < 4; q++) {
            float2 v = unpk2(acc2[i][q]);
            int col = b0 + q * 32 + tx * 2;
            *(float2*)&G[(size_t)(gi + i) * P + col] = v;
        }
    if (ti != tj) {
#pragma unroll
        for (int i = 0; i < 8; i++)
#pragma unroll
            for (int q = 0; q < 4; q++) {
                float2 v = unpk2(acc2[i][q]);
                int col = b0 + q * 32 + tx * 2;
                G[(size_t)col * P + gi + i]       = v.x;
                G[(size_t)(col + 1) * P + gi + i] = v.y;
            }
    }
}

// --------- assemble ---------------------------------------------------------
__global__ __launch_bounds__(256) void k_assemble(int m, float pf) {
    int idx4 = blockIdx.x * blockDim.x + threadIdx.x;
    if (idx4 >= P * P / 4) return;
    int idx = idx4 * 4;
    int r = idx >> 9, c0 = idx & 511;
    int kv = d_kval;
    float dg[4];
#pragma unroll
    for (int q = 0; q < 4; q++) dg[q] = (r == c0 + q) ? 1.f : 0.f;
    float sum[4] = {0.f, 0.f, 0.f, 0.f};
    for (int j = 0; j < kv; j++) {
        float4 g0 = *(const float4*)&d_Gk[0][j][idx];
        float4 g1 = *(const float4*)&d_Gk[1][j][idx];
        float4 g2 = *(const float4*)&d_Gk[2][j][idx];
        float g[4];
        g[0] = g0.x + g1.x + g2.x; g[1] = g0.y + g1.y + g2.y;
        g[2] = g0.z + g1.z + g2.z; g[3] = g0.w + g1.w + g2.w;
        float scal = pf / (((float)d_cnt[j] + 1e-8f) * 0.01f);
        float4 o;
        o.x = dg[0] + scal * g[0]; o.y = dg[1] + scal * g[1];
        o.z = dg[2] + scal * g[2]; o.w = dg[3] + scal * g[3];
        *(float4*)&d_A[j][idx] = o;
#pragma unroll
        for (int q = 0; q < 4; q++) sum[q] += g[q];
    }
    float scalar = pf / ((float)m * 0.01f);
    float4 o;
    o.x = dg[0] + scalar * sum[0]; o.y = dg[1] + scalar * sum[1];
    o.z = dg[2] + scalar * sum[2]; o.w = dg[3] + scalar * sum[3];
    *(float4*)&d_A[kv][idx] = o;
}

// ---- diag core: factor + per-block 8x8 inverses, logdet, Z=L^-1 -----------
// scr: sRed [64,128), sW8 [128,640), sInv8 [640,640+8*72)
__device__ void diag_core(int mb, int sidx, int tid, float* sD, float* sZ,
                          float* scr) {
    float* sRed  = scr + 64;
    float* sW8   = scr + 128;
    float* sInv8 = scr + 640;      // [8 blocks][8][9]
    bool needZ = (sidx < NSTEP - 1);
    if (needZ)
        for (int l = tid; l < NB * 65; l += 256) sZ[l] = 0.f;
    __syncthreads();

#pragma unroll 1
    for (int b = 0; b < NB; b += 8) {
        float* inv8 = sInv8 + (b >> 3) * 72;
        // ---- tid0: factor 8x8 in regs + invert ----
        if (tid == 0) {
            float a[8][8], ri[8];
#pragma unroll
            for (int i = 0; i < 8; i++)
#pragma unroll
                for (int u = 0; u <= i; u++)
                    a[i][u] = sD[(b + i) * 65 + b + u];
#pragma unroll
            for (int t = 0; t < 8; t++) {
                float rinv = rsqrtf(a[t][t]);
                ri[t] = rinv;
                a[t][t] *= rinv;
#pragma unroll
                for (int i = t + 1; i < 8; i++) a[i][t] *= rinv;
#pragma unroll
                for (int u = t + 1; u < 8; u++)
#pragma unroll
                    for (int i = u; i < 8; i++)
                        a[i][u] = fmaf(-a[i][t], a[u][t], a[i][u]);
            }
            // binv = inv(L8), lower
            float binv[8][8];
#pragma unroll
            for (int j = 0; j < 8; j++) {
                binv[j][j] = ri[j];
#pragma unroll
                for (int i = j + 1; i < 8; i++) {
                    float acc = 0.f;
#pragma unroll
                    for (int u = 0; u < 8; u++)
                        if (u >= j && u < i)
                            acc = fmaf(a[i][u], binv[u][j], acc);
                    binv[i][j] = -acc * ri[i];
                }
            }
#pragma unroll
            for (int i = 0; i < 8; i++) {
#pragma unroll
                for (int u = 0; u <= i; u++)
                    sD[(b + i) * 65 + b + u] = a[i][u];
#pragma unroll
                for (int u = 0; u < 8; u++)
                    inv8[i * 9 + u] = (u <= i) ? binv[i][u] : 0.f;
            }
        }
        __syncthreads();

        int rows = NB - b - 8;
        if (rows > 0) {
            // panel: x_new = x * inv8^T — dense, no serial chain
            if (tid < rows) {
                int r = b + 8 + tid;
                float x[8], y[8];
#pragma unroll
                for (int t = 0; t < 8; t++) x[t] = sD[r * 65 + b + t];
#pragma unroll
                for (int t = 0; t < 8; t++) {
                    float acc = 0.f;
#pragma unroll
                    for (int u = 0; u <= t; u++)
                        acc = fmaf(x[u], inv8[t * 9 + u], acc);
                    y[t] = acc;
                }
#pragma unroll
                for (int t = 0; t < 8; t++) sD[r * 65 + b + t] = y[t];
            }
            __syncthreads();

            // rank-8 update, lower triangle only
            int total = rows << 6;
            for (int l = tid; l < total; l += 256) {
                int i = b + 8 + (l >> 6), u = l & 63;
                if (u >= b + 8 && u <= i) {
                    float acc = sD[i * 65 + u];
#pragma unroll
                    for (int t = 0; t < 8; t++)
                        acc = fmaf(-sD[i * 65 + b + t], sD[u * 65 + b + t],
                                   acc);
                    sD[i * 65 + u] = acc;
                }
            }
        }
        __syncthreads();
    }

    if (tid < NB) sRed[tid] = logf(sD[tid * 65 + tid]);
    __syncthreads();
    if (tid < 32) {
        double lsum = (double)sRed[tid] + (double)sRed[tid + 32];
#pragma unroll
        for (int o = 16; o > 0; o >>= 1)
            lsum += __shfl_down_sync(0xffffffffu, lsum, o);
        if (tid == 0) d_hldd[mb] += lsum;
    }
    if (!needZ) return;

    // Z = L^{-1}: rank-8 panels; triangular part via inv8 (dense MAC)
    for (int b = 0; b < NB; b += 8) {
        const float* inv8 = sInv8 + (b >> 3) * 72;
        {
            int t0 = tid >> 6;
            int j = tid & 63;
#pragma unroll
            for (int pass = 0; pass < 2; pass++) {
                int t = t0 + pass * 4;
                float acc = 0.f;
                for (int u = 0; u < b; u++)
                    acc = fmaf(sD[(b + t) * 65 + u], sZ[u * 65 + j], acc);
                sW8[t * 64 + j] = acc;
            }
        }
        __syncthreads();
        if (tid < b + 8 && tid < 64) {
            int j = tid;
            float rhs[8];
#pragma unroll
            for (int t = 0; t < 8; t++)
                rhs[t] = ((b + t == j) ? 1.f : 0.f) - sW8[t * 64 + j];
#pragma unroll
            for (int r = 0; r < 8; r++) {
                float acc = 0.f;
#pragma unroll
                for (int t = 0; t <= r; t++)
                    acc = fmaf(inv8[r * 9 + t], rhs[t], acc);
                sZ[(b + r) * 65 + j] = acc;
            }
        }
        __syncthreads();
    }
}

// ---- W GEMM: sWout[t][c] = sum_u Z[t][u] * AT[u][c] -----------------------
__device__ __forceinline__ void w_gemm(const float* sZ, const float* sAT,
                                       float* sWout, int tx, int ty) {
    ull acc2[4][2];
#pragma unroll
    for (int i = 0; i < 4; i++) { acc2[i][0] = 0ull; acc2[i][1] = 0ull; }
#pragma unroll 8
    for (int u = 0; u < NB; u++) {
        float4 bv = *(const float4*)&sAT[u * DP + tx * 4];
        ull b0 = pack2(bv.x, bv.y), b1 = pack2(bv.z, bv.w);
        ull a0 = dup2(sZ[(ty * 4 + 0) * 65 + u]);
        ull a1 = dup2(sZ[(ty * 4 + 1) * 65 + u]);
        ull a2 = dup2(sZ[(ty * 4 + 2) * 65 + u]);
        ull a3 = dup2(sZ[(ty * 4 + 3) * 65 + u]);
        acc2[0][0] = ffma2(a0, b0, acc2[0][0]);
        acc2[0][1] = ffma2(a0, b1, acc2[0][1]);
        acc2[1][0] = ffma2(a1, b0, acc2[1][0]);
        acc2[1][1] = ffma2(a1, b1, acc2[1][1]);
        acc2[2][0] = ffma2(a2, b0, acc2[2][0]);
        acc2[2][1] = ffma2(a2, b1, acc2[2][1]);
        acc2[3][0] = ffma2(a3, b0, acc2[3][0]);
        acc2[3][1] = ffma2(a3, b1, acc2[3][1]);
    }
#pragma unroll
    for (int q = 0; q < 4; q++) {
        float2 lo = unpk2(acc2[q][0]), hi = unpk2(acc2[q][1]);
        float4 v; v.x = lo.x; v.y = lo.y; v.z = hi.x; v.w = hi.y;
        *(float4*)&sWout[(ty * 4 + q) * DP + tx * 4] = v;
    }
}

__device__ __forceinline__ void at_load(const float* A, int r0, int sc,
                                        float* sAT, int tid) {
    int j = tid >> 2, u0 = (tid & 3) * 16;
    const float* row = &A[(size_t)(r0 + j) * P + sc];
#pragma unroll
    for (int q4 = 0; q4 < 4; q4++) {
        float4 v = *(const float4*)&row[u0 + q4 * 4];
        int u = u0 + q4 * 4;
        sAT[(u + 0) * DP + j] = v.x;
        sAT[(u + 1) * DP + j] = v.y;
        sAT[(u + 2) * DP + j] = v.z;
        sAT[(u + 3) * DP + j] = v.w;
    }
}

__device__ __forceinline__ void tile_gemm(const float* sWi, const float* sWj,
                                          int tx, int ty, ull acc2[4][2]) {
#pragma unroll
    for (int i = 0; i < 4; i++) { acc2[i][0] = 0ull; acc2[i][1] = 0ull; }
#pragma unroll 8
    for (int t = 0; t < NB; t++) {
        float4 av = *(const float4*)&sWi[t * DP + ty * 4];
        float4 bv = *(const float4*)&sWj[t * DP + tx * 4];
        ull b0 = pack2(bv.x, bv.y), b1 = pack2(bv.z, bv.w);
        ull a0 = dup2(av.x), a1 = dup2(av.y);
        ull a2 = dup2(av.z), a3 = dup2(av.w);
        acc2[0][0] = ffma2(a0, b0, acc2[0][0]);
        acc2[0][1] = ffma2(a0, b1, acc2[0][1]);
        acc2[1][0] = ffma2(a1, b0, acc2[1][0]);
        acc2[1][1] = ffma2(a1, b1, acc2[1][1]);
        acc2[2][0] = ffma2(a2, b0, acc2[2][0]);
        acc2[2][1] = ffma2(a2, b1, acc2[2][1]);
        acc2[3][0] = ffma2(a3, b0, acc2[3][0]);
        acc2[3][1] = ffma2(a3, b1, acc2[3][1]);
    }
}

// ---- k_chol: persistent, pure dataflow ------------------------------------
__global__ __launch_bounds__(256) void k_chol(float* out, int m) {
    int cx = blockIdx.x;
    int mb = blockIdx.y;
    if (mb > d_kval) return;
    extern __shared__ float fs[];
    int tid = threadIdx.x;
    int tx = tid & 15, ty = tid >> 4;
    float* A = d_A[mb];

    float* sZ  = fs;
    float* sAT = fs + REG;
    float* sWi = fs + 2 * REG;
    float* sWj = fs + 3 * REG;
    int* tfl = d_tflag[mb];

    if (cx == 0) {
        {
            float* sD = sAT;
            for (int l = tid; l < NB * NB; l += 256) {
                int r = l >> 6, c = l & 63;
                sD[r * 65 + c] = A[(size_t)r * P + c];
            }
            __syncthreads();
            diag_core(mb, 0, tid, sD, sZ, sWj);
            float* Zg = d_Z[0][mb];
            for (int q = tid; q < NB * 65 / 4; q += 256)
                *(float4*)&Zg[q * 4] = *(const float4*)&sZ[q * 4];
            __syncthreads();
            if (tid == 0) rel_st(&d_zflag[mb], 1);
        }
        for (int s = 0; s < NSTEP - 1; s++) {
            int sc = s * NB;
            fwait3(&tfl[(s + 1) * 8 + s], s, &tfl[(s + 1) * 8 + s + 1], s,
                   0, 0);
            at_load(A, sc + NB, sc, sAT, tid);
            __syncthreads();
            w_gemm(sZ, sAT, sWi, tx, ty);
            __syncthreads();
            ull acc2[4][2];
            tile_gemm(sWi, sWi, tx, ty, acc2);
            float* sD = sAT;
            int r0 = sc + NB;
#pragma unroll
            for (int q = 0; q < 4; q++) {
                float2 lo = unpk2(acc2[q][0]), hi = unpk2(acc2[q][1]);
                const float* row =
                    &A[(size_t)(r0 + ty * 4 + q) * P + r0 + tx * 4];
                float4 v = *(const float4*)row;
                int rr = ty * 4 + q, cc = tx * 4;
                sD[rr * 65 + cc + 0] = v.x - lo.x;
                sD[rr * 65 + cc + 1] = v.y - lo.y;
                sD[rr * 65 + cc + 2] = v.z - hi.x;
                sD[rr * 65 + cc + 3] = v.w - hi.y;
            }
            __syncthreads();
            diag_core(mb, s + 1, tid, sD, sZ, sWj);
            if (s + 1 < NSTEP - 1) {
                float* Zg = d_Z[s + 1][mb];
                for (int q = tid; q < NB * 65 / 4; q += 256)
                    *(float4*)&Zg[q * 4] = *(const float4*)&sZ[q * 4];
                __syncthreads();
                if (tid == 0) rel_st(&d_zflag[mb], s + 2);
            }
        }
        if (tid == 0) {
            rel_add(&d_done);
            if (mb == 0) {
                int kv = d_kval;
                while (acq_ld(&d_done) < kv + 1) { }
                double comp = 0.0;
                for (int j = 0; j < kv; j++) {
                    double trPi = (double)d_cnt[j] + 1e-8;
                    comp += d_hldd[j] * trPi / (double)m;
                }
                out[0] = (float)d_hldd[kv];
                out[1] = (float)comp;
                d_lbar = 0;
            }
        }
        return;
    }

    for (int s = 0; s < NSTEP - 1; s++) {
        int nblk = NSTEP - 1 - s;
        int ntile = nblk * (nblk + 1) / 2;
        int sc = s * NB;

        if (cx <= nblk && nblk > 1) {
            int panel = cx - 1;
            fwait3(&d_zflag[mb], s + 1,
                   &tfl[(s + 1 + panel) * 8 + s], s, 0, 0);
            {
                const float* Zg = d_Z[s][mb];
                for (int q = tid; q < NB * 65 / 4; q += 256)
                    *(float4*)&sZ[q * 4] = *(const float4*)&Zg[q * 4];
            }
            at_load(A, sc + NB + panel * NB, sc, sAT, tid);
            __syncthreads();
            w_gemm(sZ, sAT, sWi, tx, ty);
            __syncthreads();
            float* Wg = d_W[s][mb][panel];
            for (int q = tid; q < NB * DP / 4; q += 256)
                *(float4*)&Wg[q * 4] = *(const float4*)&sWi[q * 4];
            __syncthreads();
            if (tid == 0) rel_st(&d_wflag[mb][panel], s + 1);
        }

        for (int l = cx; l < ntile; l += NCTA - 1) {
            int ti = 0;
            while ((ti + 1) * (ti + 2) / 2 <= l) ti++;
            int tj = l - ti * (ti + 1) / 2;
            int ri = sc + NB + ti * NB, rj = sc + NB + tj * NB;
            int I = s + 1 + ti, J = s + 1 + tj;

            __syncthreads();
            fwait3(&d_wflag[mb][ti], s + 1,
                   (ti != tj) ? &d_wflag[mb][tj] : 0, s + 1,
                   &tfl[I * 8 + J], s);
            {
                const float* Wg = d_W[s][mb][ti];
                for (int q = tid; q < NB * DP / 4; q += 256)
                    *(float4*)&sWi[q * 4] = *(const float4*)&Wg[q * 4];
            }
            const float* pWj = sWi;
            if (ti != tj) {
                const float* Wg = d_W[s][mb][tj];
                for (int q = tid; q < NB * DP / 4; q += 256)
                    *(float4*)&sWj[q * 4] = *(const float4*)&Wg[q * 4];
                pWj = sWj;
            }
            __syncthreads();
            ull acc2[4][2];
            tile_gemm(sWi, pWj, tx, ty, acc2);
#pragma unroll
            for (int q = 0; q < 4; q++) {
                float2 lo = unpk2(acc2[q][0]), hi = unpk2(acc2[q][1]);
                float* row = &A[(size_t)(ri + ty * 4 + q) * P + rj + tx * 4];
                float4 v = *(float4*)row;
                v.x -= lo.x; v.y -= lo.y; v.z -= hi.x; v.w -= hi.y;
                *(float4*)row = v;
            }
            __syncthreads();
            if (tid == 0) rel_st(&tfl[I * 8 + J], s + 1);
        }
    }
}

// ---------------- launch ----------------------------------------------------
extern "C" void kernel_launch(void* const* d_in, const int* in_sizes, int n_in,
                              void* d_out, int out_size) {
    const float* X    = (const float*)d_in[0];
    const void*  Y    = d_in[1];
    const int*   ncls = (n_in >= 3) ? (const int*)d_in[2] : nullptr;
    int m = in_sizes[1];
    int p = in_sizes[0] / m;          // 512
    float* out = (float*)d_out;
    (void)out_size;
    int nchunk = (m + 255) / 256;

    cudaFuncSetAttribute(k_chol, cudaFuncAttributeMaxDynamicSharedMemorySize,
                         FT_SMEM_BYTES);

    k_labels<<<nchunk, 256>>>(Y, ncls, m, nchunk);
    k_gram<<<dim3(10, K_MAX, NSLICE), 256>>>(X, p);
    k_assemble<<<(P * P / 4 + 255) / 256, 256>>>(m, (float)p);
    k_chol<<<dim3(NCTA, NM), 256, FT_SMEM_BYTES>>>(out, m);
}

// round 16
// speedup vs baseline: 1.2437x; 1.2437x over previous
#include <cuda_runtime.h>
#include <math.h>

#define P       512
#define K_MAX   16
#define NM      (K_MAX + 1)
#define M_CAP   65536
#define NCH_MAX 256
#define NB      64
#define NSTEP   (P / NB)      // 8
#define NSLICE  3
#define DP      68
#define NCTA    15
#define REG     4352          // smem region stride (floats)

#define FT_SMEM_BYTES (4 * REG * 4)   // 69632 B

typedef unsigned long long ull;

// ---------------- f32x2 packed helpers (Blackwell sm_103a) -----------------
__device__ __forceinline__ ull ffma2(ull a, ull b, ull c) {
    ull d;
    asm("fma.rn.f32x2 %0, %1, %2, %3;" : "=l"(d) : "l"(a), "l"(b), "l"(c));
    return d;
}
__device__ __forceinline__ ull dup2(float x) {
    ull r; unsigned xb = __float_as_uint(x);
    asm("mov.b64 %0, {%1, %2};" : "=l"(r) : "r"(xb), "r"(xb));
    return r;
}
__device__ __forceinline__ ull pack2(float lo, float hi) {
    ull r;
    asm("mov.b64 %0, {%1, %2};" : "=l"(r) : "f"(lo), "f"(hi));
    return r;
}
__device__ __forceinline__ float2 unpk2(ull v) {
    float2 r;
    asm("mov.b64 {%0, %1}, %2;" : "=f"(r.x), "=f"(r.y) : "l"(v));
    return r;
}

// ---------------- device scratch -------------------------------------------
__device__ int    d_cnt[K_MAX];
__device__ int    d_kval;
__device__ int    d_idx[M_CAP];
__device__ int    d_bh[NCH_MAX][K_MAX];
__device__ int    d_boff[NCH_MAX][K_MAX];
__device__ int    d_cstart[K_MAX];
__device__ int    d_lbar;
__device__ int    d_done;
__device__ int    d_zflag[NM];
__device__ int    d_wflag[NM][NSTEP - 1];
__device__ int    d_tflag[NM][64];
__device__ float  d_Gk[NSLICE][K_MAX][P * P];
__device__ float  d_A[NM][P * P];
__device__ float  d_Z[NSTEP][NM][NB * 65];
__device__ float  d_W[NSTEP - 1][NM][NSTEP - 1][NB * DP];
__device__ double d_hldd[NM];

// ---------------- release/acquire primitives -------------------------------
__device__ __forceinline__ void rel_add(int* p) {
    int d;
    asm volatile("atom.release.gpu.add.s32 %0, [%1], 1;"
                 : "=r"(d) : "l"(p) : "memory");
}
__device__ __forceinline__ void rel_st(int* p, int v) {
    asm volatile("st.release.gpu.s32 [%0], %1;" :: "l"(p), "r"(v) : "memory");
}
__device__ __forceinline__ int acq_ld(const int* p) {
    int v;
    asm volatile("ld.acquire.gpu.s32 %0, [%1];" : "=r"(v) : "l"(p) : "memory");
    return v;
}
__device__ __forceinline__ void gbar(int nb, int ep) {
    __syncthreads();
    if (threadIdx.x == 0) {
        rel_add(&d_lbar);
        while (acq_ld(&d_lbar) < nb * ep) { }
    }
    __syncthreads();
}
__device__ __forceinline__ void fwait3(const int* p0, int v0,
                                       const int* p1, int v1,
                                       const int* p2, int v2) {
    if (threadIdx.x == 0) {
        if (p0) while (acq_ld(p0) < v0) { }
        if (p1) while (acq_ld(p1) < v1) { }
        if (p2) while (acq_ld(p2) < v2) { }
    }
    __syncthreads();
}

// ------- k_labels: dtype detect + hist + scan + stable scatter -------------
__global__ __launch_bounds__(256) void k_labels(const void* __restrict__ Y,
                                                const int* ncls, int m,
                                                int nchunk) {
    __shared__ int sh[K_MAX];
    __shared__ int swh[8 * K_MAX];
    __shared__ int nzf;
    int tid = threadIdx.x;
    int b = blockIdx.x;
    if (tid == 0) nzf = 0;
    if (tid < K_MAX) sh[tid] = 0;
    __syncthreads();

    int lim = m / 2; if (lim > 512) lim = 512;
    int found = 0;
    for (int i = tid; i < lim; i += 256)
        if (((const int*)Y)[2 * i + 1] != 0) found = 1;
    if (__any_sync(0xffffffffu, found)) {
        if ((tid & 31) == 0) atomicOr(&nzf, 1);
    }
    __syncthreads();
    int is64 = nzf ? 0 : 1;

    int i = b * 256 + tid;
    int c = -1;
    if (i < m) {
        c = is64 ? (int)((const long long*)Y)[i] : ((const int*)Y)[i];
        if (c < 0 || c >= K_MAX) c = 0;
        atomicAdd(&sh[c], 1);
    }
    __syncthreads();
    if (tid < K_MAX) d_bh[b][tid] = sh[tid];

    gbar(nchunk, 1);

    if (b == 0) {
        if (tid < K_MAX) {
            int run = 0;
            for (int bb = 0; bb < nchunk; bb++) {
                d_boff[bb][tid] = run;
                run += d_bh[bb][tid];
            }
            d_cnt[tid] = run;
            sh[tid] = run;
        }
        __syncthreads();
        if (tid == 0) {
            int run = 0;
            for (int cc = 0; cc < K_MAX; cc++) {
                d_cstart[cc] = run;
                run += sh[cc];
            }
            int k = ncls ? *ncls : 10;
            if (k < 1) k = 1;
            if (k > K_MAX) k = K_MAX;
            d_kval = k;
            d_done = 0;
        }
        if (tid < NM) { d_hldd[tid] = 0.0; d_zflag[tid] = 0; }
        for (int q = tid; q < NM * (NSTEP - 1); q += 256)
            ((int*)d_wflag)[q] = 0;
        for (int q = tid; q < NM * 64; q += 256)
            ((int*)d_tflag)[q] = 0;
    }

    gbar(nchunk, 2);

    if (tid < 8 * K_MAX) swh[tid] = 0;
    __syncthreads();
    int lane = tid & 31, w = tid >> 5;
    unsigned mask = __match_any_sync(0xffffffffu, c);
    int rin = __popc(mask & ((1u << lane) - 1u));
    int leader = __ffs(mask) - 1;
    if (c >= 0 && lane == leader) swh[w * K_MAX + c] = __popc(mask);
    __syncthreads();
    if (c >= 0) {
        int pre = 0;
        for (int w2 = 0; w2 < w; w2++) pre += swh[w2 * K_MAX + c];
        d_idx[d_cstart[c] + d_boff[b][c] + pre + rin] = i;
    }
}

// ------- per-class Gram: dense gather over sorted class range --------------
__global__ __launch_bounds__(256) void k_gram(const float* __restrict__ X,
                                              int p) {
    int c = blockIdx.y;
    if (c >= d_kval) return;
    int tile = blockIdx.x;
    int ti = 0;
    while ((ti + 1) * (ti + 2) / 2 <= tile) ti++;
    int tj = tile - ti * (ti + 1) / 2;
    int a0 = ti * 128, b0 = tj * 128;
    int z = blockIdx.z;
    int cstart = d_cstart[c], ccnt = d_cnt[c];
    int sb = (int)((long long)ccnt * z / NSLICE);
    int se = (int)((long long)ccnt * (z + 1) / NSLICE);

    __shared__ __align__(16) float sA[32][132];
    __shared__ __align__(16) float sB[32][132];
    __shared__ int sidx[32];

    int tid = threadIdx.x;
    int tx = tid & 15, ty = tid >> 4;
    int lt = tid >> 3, lc = tid & 7;

    ull acc2[8][4];
#pragma unroll
    for (int i = 0; i < 8; i++)
#pragma unroll
        for (int q = 0; q < 4; q++) acc2[i][q] = 0ull;

    for (int base = sb; base < se; base += 32) {
        int nv = se - base;
        if (nv > 32) nv = 32;
        __syncthreads();
        if (tid < 32)
            sidx[tid] = (tid < nv) ? d_idx[cstart + base + tid] : -1;
        __syncthreads();
        {
            int s = sidx[lt];
            if (s >= 0) {
                const float* xr = X + (size_t)s * p;
#pragma unroll
                for (int q = 0; q < 4; q++) {
                    int col = lc * 16 + q * 4;
                    *(float4*)&sA[lt][col] = *(const float4*)&xr[a0 + col];
                    *(float4*)&sB[lt][col] = *(const float4*)&xr[b0 + col];
                }
            }
        }
        __syncthreads();

        for (int t = 0; t < nv; t++) {
            float a[8];
            ull ad[8], b2[4];
            *(float4*)&a[0] = *(const float4*)&sA[t][ty * 8];
            *(float4*)&a[4] = *(const float4*)&sA[t][ty * 8 + 4];
#pragma unroll
            for (int i = 0; i < 8; i++) ad[i] = dup2(a[i]);
#pragma unroll
            for (int q = 0; q < 4; q++)
                b2[q] = *(const ull*)&sB[t][tx * 2 + q * 32];
#pragma unroll
            for (int i = 0; i < 8; i++)
#pragma unroll
                for (int q = 0; q < 4; q++)
                    acc2[i][q] = ffma2(ad[i], b2[q], acc2[i][q]);
        }
    }

    float* G = d_Gk[z][c];
    int gi = a0 + ty * 8;
#pragma unroll
    for (int i = 0; i < 8; i++)
#pragma unroll
        for (int q = 0; q < 4; q++) {
            float2 v = unpk2(acc2[i][q]);
            int col = b0 + q * 32 + tx * 2;
            *(float2*)&G[(size_t)(gi + i) * P + col] = v;
        }
    if (ti != tj) {
#pragma unroll
        for (int i = 0; i < 8; i++)
#pragma unroll
            for (int q = 0; q < 4; q++) {
                float2 v = unpk2(acc2[i][q]);
                int col = b0 + q * 32 + tx * 2;
                G[(size_t)col * P + gi + i]       = v.x;
                G[(size_t)(col + 1) * P + gi + i] = v.y;
            }
    }
}

// --------- assemble ---------------------------------------------------------
__global__ __launch_bounds__(256) void k_assemble(int m, float pf) {
    int idx4 = blockIdx.x * blockDim.x + threadIdx.x;
    if (idx4 >= P * P / 4) return;
    int idx = idx4 * 4;
    int r = idx >> 9, c0 = idx & 511;
    int kv = d_kval;
    float dg[4];
#pragma unroll
    for (int q = 0; q < 4; q++) dg[q] = (r == c0 + q) ? 1.f : 0.f;
    float sum[4] = {0.f, 0.f, 0.f, 0.f};
    for (int j = 0; j < kv; j++) {
        float4 g0 = *(const float4*)&d_Gk[0][j][idx];
        float4 g1 = *(const float4*)&d_Gk[1][j][idx];
        float4 g2 = *(const float4*)&d_Gk[2][j][idx];
        float g[4];
        g[0] = g0.x + g1.x + g2.x; g[1] = g0.y + g1.y + g2.y;
        g[2] = g0.z + g1.z + g2.z; g[3] = g0.w + g1.w + g2.w;
        float scal = pf / (((float)d_cnt[j] + 1e-8f) * 0.01f);
        float4 o;
        o.x = dg[0] + scal * g[0]; o.y = dg[1] + scal * g[1];
        o.z = dg[2] + scal * g[2]; o.w = dg[3] + scal * g[3];
        *(float4*)&d_A[j][idx] = o;
#pragma unroll
        for (int q = 0; q < 4; q++) sum[q] += g[q];
    }
    float scalar = pf / ((float)m * 0.01f);
    float4 o;
    o.x = dg[0] + scalar * sum[0]; o.y = dg[1] + scalar * sum[1];
    o.z = dg[2] + scalar * sum[2]; o.w = dg[3] + scalar * sum[3];
    *(float4*)&d_A[kv][idx] = o;
}

// ---- diag core (R14 version): factor 64x64, logdet, Z=L^-1 ----------------
__device__ void diag_core(int mb, int sidx, int tid, float* sD, float* sZ,
                          float* scr) {
    float* sdinv = scr;
    float* sRed  = scr + 64;
    float* sW8   = scr + 128;
    bool needZ = (sidx < NSTEP - 1);
    if (needZ)
        for (int l = tid; l < NB * 65; l += 256) sZ[l] = 0.f;
    __syncthreads();

#pragma unroll 1
    for (int b = 0; b < NB; b += 8) {
        if (tid == 0) {
            float a[8][8];
#pragma unroll
            for (int i = 0; i < 8; i++)
#pragma unroll
                for (int u = 0; u <= i; u++)
                    a[i][u] = sD[(b + i) * 65 + b + u];
#pragma unroll
            for (int t = 0; t < 8; t++) {
                float rinv = rsqrtf(a[t][t]);
                a[t][t] *= rinv;
                sdinv[b + t] = rinv;
#pragma unroll
                for (int i = t + 1; i < 8; i++) a[i][t] *= rinv;
#pragma unroll
                for (int u = t + 1; u < 8; u++)
#pragma unroll
                    for (int i = u; i < 8; i++)
                        a[i][u] = fmaf(-a[i][t], a[u][t], a[i][u]);
            }
#pragma unroll
            for (int i = 0; i < 8; i++)
#pragma unroll
                for (int u = 0; u <= i; u++)
                    sD[(b + i) * 65 + b + u] = a[i][u];
        }
        __syncthreads();

        int rows = NB - b - 8;
        if (rows > 0) {
            if (tid < rows) {
                int r = b + 8 + tid;
                float x[8];
#pragma unroll
                for (int t = 0; t < 8; t++) x[t] = sD[r * 65 + b + t];
#pragma unroll
                for (int t = 0; t < 8; t++) {
                    float v = x[t];
#pragma unroll
                    for (int u = 0; u < t; u++)
                        v = fmaf(-x[u], sD[(b + t) * 65 + b + u], v);
                    x[t] = v * sdinv[b + t];
                }
#pragma unroll
                for (int t = 0; t < 8; t++) sD[r * 65 + b + t] = x[t];
            }
            __syncthreads();

            int total = rows << 6;
            for (int l = tid; l < total; l += 256) {
                int i = b + 8 + (l >> 6), u = l & 63;
                if (u >= b + 8 && u <= i) {
                    float acc = sD[i * 65 + u];
#pragma unroll
                    for (int t = 0; t < 8; t++)
                        acc = fmaf(-sD[i * 65 + b + t], sD[u * 65 + b + t],
                                   acc);
                    sD[i * 65 + u] = acc;
                }
            }
        }
        __syncthreads();
    }

    if (tid < NB) sRed[tid] = logf(sD[tid * 65 + tid]);
    __syncthreads();
    if (tid < 32) {
        double lsum = (double)sRed[tid] + (double)sRed[tid + 32];
#pragma unroll
        for (int o = 16; o > 0; o >>= 1)
            lsum += __shfl_down_sync(0xffffffffu, lsum, o);
        if (tid == 0) d_hldd[mb] += lsum;
    }
    if (!needZ) return;

    for (int b = 0; b < NB; b += 8) {
        {
            int t0 = tid >> 6;
            int j = tid & 63;
#pragma unroll
            for (int pass = 0; pass < 2; pass++) {
                int t = t0 + pass * 4;
                float acc = 0.f;
                for (int u = 0; u < b; u++)
                    acc = fmaf(sD[(b + t) * 65 + u], sZ[u * 65 + j], acc);
                sW8[t * 64 + j] = acc;
            }
        }
        __syncthreads();
        if (tid < 64) {
            int j = tid;
#pragma unroll
            for (int t = 0; t < 8; t++) {
                int r = b + t;
                if (j <= r) {
                    float v = ((r == j) ? 1.f : 0.f) - sW8[t * 64 + j];
#pragma unroll
                    for (int u = 0; u < 8; u++) {
                        if (u < t)
                            v = fmaf(-sD[r * 65 + b + u], sZ[(b + u) * 65 + j],
                                     v);
                    }
                    sZ[r * 65 + j] = v * sdinv[r];
                }
            }
        }
        __syncthreads();
    }
}

// ---- W GEMM: sWout[t][c] = sum_u Z[t][u] * AT[u][c] -----------------------
__device__ __forceinline__ void w_gemm(const float* sZ, const float* sAT,
                                       float* sWout, int tx, int ty) {
    ull acc2[4][2];
#pragma unroll
    for (int i = 0; i < 4; i++) { acc2[i][0] = 0ull; acc2[i][1] = 0ull; }
#pragma unroll 8
    for (int u = 0; u < NB; u++) {
        float4 bv = *(const float4*)&sAT[u * DP + tx * 4];
        ull b0 = pack2(bv.x, bv.y), b1 = pack2(bv.z, bv.w);
        ull a0 = dup2(sZ[(ty * 4 + 0) * 65 + u]);
        ull a1 = dup2(sZ[(ty * 4 + 1) * 65 + u]);
        ull a2 = dup2(sZ[(ty * 4 + 2) * 65 + u]);
        ull a3 = dup2(sZ[(ty * 4 + 3) * 65 + u]);
        acc2[0][0] = ffma2(a0, b0, acc2[0][0]);
        acc2[0][1] = ffma2(a0, b1, acc2[0][1]);
        acc2[1][0] = ffma2(a1, b0, acc2[1][0]);
        acc2[1][1] = ffma2(a1, b1, acc2[1][1]);
        acc2[2][0] = ffma2(a2, b0, acc2[2][0]);
        acc2[2][1] = ffma2(a2, b1, acc2[2][1]);
        acc2[3][0] = ffma2(a3, b0, acc2[3][0]);
        acc2[3][1] = ffma2(a3, b1, acc2[3][1]);
    }
#pragma unroll
    for (int q = 0; q < 4; q++) {
        float2 lo = unpk2(acc2[q][0]), hi = unpk2(acc2[q][1]);
        float4 v; v.x = lo.x; v.y = lo.y; v.z = hi.x; v.w = hi.y;
        *(float4*)&sWout[(ty * 4 + q) * DP + tx * 4] = v;
    }
}

__device__ __forceinline__ void at_load(const float* A, int r0, int sc,
                                        float* sAT, int tid) {
    int j = tid >> 2, u0 = (tid & 3) * 16;
    const float* row = &A[(size_t)(r0 + j) * P + sc];
#pragma unroll
    for (int q4 = 0; q4 < 4; q4++) {
        float4 v = *(const float4*)&row[u0 + q4 * 4];
        int u = u0 + q4 * 4;
        sAT[(u + 0) * DP + j] = v.x;
        sAT[(u + 1) * DP + j] = v.y;
        sAT[(u + 2) * DP + j] = v.z;
        sAT[(u + 3) * DP + j] = v.w;
    }
}

__device__ __forceinline__ void tile_gemm(const float* sWi, const float* sWj,
                                          int tx, int ty, ull acc2[4][2]) {
#pragma unroll
    for (int i = 0; i < 4; i++) { acc2[i][0] = 0ull; acc2[i][1] = 0ull; }
#pragma unroll 8
    for (int t = 0; t < NB; t++) {
        float4 av = *(const float4*)&sWi[t * DP + ty * 4];
        float4 bv = *(const float4*)&sWj[t * DP + tx * 4];
        ull b0 = pack2(bv.x, bv.y), b1 = pack2(bv.z, bv.w);
        ull a0 = dup2(av.x), a1 = dup2(av.y);
        ull a2 = dup2(av.z), a3 = dup2(av.w);
        acc2[0][0] = ffma2(a0, b0, acc2[0][0]);
        acc2[0][1] = ffma2(a0, b1, acc2[0][1]);
        acc2[1][0] = ffma2(a1, b0, acc2[1][0]);
        acc2[1][1] = ffma2(a1, b1, acc2[1][1]);
        acc2[2][0] = ffma2(a2, b0, acc2[2][0]);
        acc2[2][1] = ffma2(a2, b1, acc2[2][1]);
        acc2[3][0] = ffma2(a3, b0, acc2[3][0]);
        acc2[3][1] = ffma2(a3, b1, acc2[3][1]);
    }
}

// RMW a 64x64 tile of A with -acc, then release its tflag
__device__ __forceinline__ void tile_rmw(float* A, int ri, int rj, int tx,
                                         int ty, ull acc2[4][2]) {
#pragma unroll
    for (int q = 0; q < 4; q++) {
        float2 lo = unpk2(acc2[q][0]), hi = unpk2(acc2[q][1]);
        float* row = &A[(size_t)(ri + ty * 4 + q) * P + rj + tx * 4];
        float4 v = *(float4*)row;
        v.x -= lo.x; v.y -= lo.y; v.z -= hi.x; v.w -= hi.y;
        *(float4*)row = v;
    }
}

// ---- k_chol: persistent dataflow + dedicated lookahead CTA1 ---------------
__global__ __launch_bounds__(256) void k_chol(float* out, int m) {
    int cx = blockIdx.x;
    int mb = blockIdx.y;
    if (mb > d_kval) return;
    extern __shared__ float fs[];
    int tid = threadIdx.x;
    int tx = tid & 15, ty = tid >> 4;
    float* A = d_A[mb];

    float* sZ  = fs;
    float* sAT = fs + REG;
    float* sWi = fs + 2 * REG;
    float* sWj = fs + 3 * REG;
    int* tfl = d_tflag[mb];

    if (cx == 0) {
        // ---- CTA0: critical chain ----
        {
            float* sD = sAT;
            for (int l = tid; l < NB * NB; l += 256) {
                int r = l >> 6, c = l & 63;
                sD[r * 65 + c] = A[(size_t)r * P + c];
            }
            __syncthreads();
            diag_core(mb, 0, tid, sD, sZ, sWj);
            float* Zg = d_Z[0][mb];
            for (int q = tid; q < NB * 65 / 4; q += 256)
                *(float4*)&Zg[q * 4] = *(const float4*)&sZ[q * 4];
            __syncthreads();
            if (tid == 0) rel_st(&d_zflag[mb], 1);
        }
        for (int s = 0; s < NSTEP - 1; s++) {
            int sc = s * NB;
            fwait3(&tfl[(s + 1) * 8 + s], s, &tfl[(s + 1) * 8 + s + 1], s,
                   0, 0);
            at_load(A, sc + NB, sc, sAT, tid);
            __syncthreads();
            w_gemm(sZ, sAT, sWi, tx, ty);
            __syncthreads();
            ull acc2[4][2];
            tile_gemm(sWi, sWi, tx, ty, acc2);
            float* sD = sAT;
            int r0 = sc + NB;
#pragma unroll
            for (int q = 0; q < 4; q++) {
                float2 lo = unpk2(acc2[q][0]), hi = unpk2(acc2[q][1]);
                const float* row =
                    &A[(size_t)(r0 + ty * 4 + q) * P + r0 + tx * 4];
                float4 v = *(const float4*)row;
                int rr = ty * 4 + q, cc = tx * 4;
                sD[rr * 65 + cc + 0] = v.x - lo.x;
                sD[rr * 65 + cc + 1] = v.y - lo.y;
                sD[rr * 65 + cc + 2] = v.z - hi.x;
                sD[rr * 65 + cc + 3] = v.w - hi.y;
            }
            __syncthreads();
            diag_core(mb, s + 1, tid, sD, sZ, sWj);
            if (s + 1 < NSTEP - 1) {
                float* Zg = d_Z[s + 1][mb];
                for (int q = tid; q < NB * 65 / 4; q += 256)
                    *(float4*)&Zg[q * 4] = *(const float4*)&sZ[q * 4];
                __syncthreads();
                if (tid == 0) rel_st(&d_zflag[mb], s + 2);
            }
        }
        if (tid == 0) {
            rel_add(&d_done);
            if (mb == 0) {
                int kv = d_kval;
                while (acq_ld(&d_done) < kv + 1) { }
                double comp = 0.0;
                for (int j = 0; j < kv; j++) {
                    double trPi = (double)d_cnt[j] + 1e-8;
                    comp += d_hldd[j] * trPi / (double)m;
                }
                out[0] = (float)d_hldd[kv];
                out[1] = (float)comp;
                d_lbar = 0;
            }
        }
        return;
    }

    if (cx == 1) {
        // ---- lookahead CTA: tiles (1,0) and (1,1) with local W ----
        for (int s = 0; s < NSTEP - 1; s++) {
            int nblk = NSTEP - 1 - s;
            if (nblk < 2) break;          // tiles 1,2 don't exist
            int sc = s * NB;
            int I = s + 2;
            // need Z(s), and A blocks (I,s+1),(I,I) updated through s-1,
            // plus A panels (s+1,s),(I,s) for W (guarded by CTA0's wait
            // already for (s+1,s); (I,s) needs its own wait)
            fwait3(&d_zflag[mb], s + 1, &tfl[I * 8 + s + 1], s,
                   &tfl[I * 8 + I], s);
            fwait3(&tfl[I * 8 + s], s, 0, 0, 0, 0);
            {
                const float* Zg = d_Z[s][mb];
                for (int q = tid; q < NB * 65 / 4; q += 256)
                    *(float4*)&sZ[q * 4] = *(const float4*)&Zg[q * 4];
            }
            // W0 = Z * A(s+1,s)^T
            at_load(A, sc + NB, sc, sAT, tid);
            __syncthreads();
            w_gemm(sZ, sAT, sWi, tx, ty);
            __syncthreads();
            // W1 = Z * A(I,s)^T
            at_load(A, sc + 2 * NB, sc, sAT, tid);
            __syncthreads();
            w_gemm(sZ, sAT, sWj, tx, ty);
            __syncthreads();
            // tile (1,0): A(I,s+1) -= W1^T W0
            {
                ull acc2[4][2];
                tile_gemm(sWj, sWi, tx, ty, acc2);
                tile_rmw(A, sc + 2 * NB, sc + NB, tx, ty, acc2);
                __syncthreads();
                if (tid == 0) rel_st(&tfl[I * 8 + s + 1], s + 1);
            }
            // tile (1,1): A(I,I) -= W1^T W1
            {
                ull acc2[4][2];
                tile_gemm(sWj, sWj, tx, ty, acc2);
                tile_rmw(A, sc + 2 * NB, sc + 2 * NB, tx, ty, acc2);
                __syncthreads();
                if (tid == 0) rel_st(&tfl[I * 8 + I], s + 1);
            }
        }
        return;
    }

    // ---- bulk workers (cx = 2..14): shared-W producers + consumers --------
    for (int s = 0; s < NSTEP - 1; s++) {
        int nblk = NSTEP - 1 - s;
        int ntile = nblk * (nblk + 1) / 2;
        int sc = s * NB;

        if (cx - 2 < nblk && nblk > 2) {
            int panel = cx - 2;
            fwait3(&d_zflag[mb], s + 1,
                   &tfl[(s + 1 + panel) * 8 + s], s, 0, 0);
            {
                const float* Zg = d_Z[s][mb];
                for (int q = tid; q < NB * 65 / 4; q += 256)
                    *(float4*)&sZ[q * 4] = *(const float4*)&Zg[q * 4];
            }
            at_load(A, sc + NB + panel * NB, sc, sAT, tid);
            __syncthreads();
            w_gemm(sZ, sAT, sWi, tx, ty);
            __syncthreads();
            float* Wg = d_W[s][mb][panel];
            for (int q = tid; q < NB * DP / 4; q += 256)
                *(float4*)&Wg[q * 4] = *(const float4*)&sWi[q * 4];
            __syncthreads();
            if (tid == 0) rel_st(&d_wflag[mb][panel], s + 1);
        }

        for (int l = 3 + (cx - 2); l < ntile; l += NCTA - 2) {
            int ti = 0;
            while ((ti + 1) * (ti + 2) / 2 <= l) ti++;
            int tj = l - ti * (ti + 1) / 2;
            int ri = sc + NB + ti * NB, rj = sc + NB + tj * NB;
            int I = s + 1 + ti, J = s + 1 + tj;

            __syncthreads();
            fwait3(&d_wflag[mb][ti], s + 1,
                   (ti != tj) ? &d_wflag[mb][tj] : 0, s + 1,
                   &tfl[I * 8 + J], s);
            {
                const float* Wg = d_W[s][mb][ti];
                for (int q = tid; q < NB * DP / 4; q += 256)
                    *(float4*)&sWi[q * 4] = *(const float4*)&Wg[q * 4];
            }
            const float* pWj = sWi;
            if (ti != tj) {
                const float* Wg = d_W[s][mb][tj];
                for (int q = tid; q < NB * DP / 4; q += 256)
                    *(float4*)&sWj[q * 4] = *(const float4*)&Wg[q * 4];
                pWj = sWj;
            }
            __syncthreads();
            ull acc2[4][2];
            tile_gemm(sWi, pWj, tx, ty, acc2);
            tile_rmw(A, ri, rj, tx, ty, acc2);
            __syncthreads();
            if (tid == 0) rel_st(&tfl[I * 8 + J], s + 1);
        }
    }
}

// ---------------- launch ----------------------------------------------------
extern "C" void kernel_launch(void* const* d_in, const int* in_sizes, int n_in,
                              void* d_out, int out_size) {
    const float* X    = (const float*)d_in[0];
    const void*  Y    = d_in[1];
    const int*   ncls = (n_in >= 3) ? (const int*)d_in[2] : nullptr;
    int m = in_sizes[1];
    int p = in_sizes[0] / m;          // 512
    float* out = (float*)d_out;
    (void)out_size;
    int nchunk = (m + 255) / 256;

    cudaFuncSetAttribute(k_chol, cudaFuncAttributeMaxDynamicSharedMemorySize,
                         FT_SMEM_BYTES);

    k_labels<<<nchunk, 256>>>(Y, ncls, m, nchunk);
    k_gram<<<dim3(10, K_MAX, NSLICE), 256>>>(X, p);
    k_assemble<<<(P * P / 4 + 255) / 256, 256>>>(m, (float)p);
    k_chol<<<dim3(NCTA, NM), 256, FT_SMEM_BYTES>>>(out, m);
}

// round 17
// speedup vs baseline: 1.2928x; 1.0395x over previous
#include <cuda_runtime.h>
#include <math.h>

#define P       512
#define K_MAX   16
#define NM      (K_MAX + 1)
#define M_CAP   65536
#define NCH_MAX 256
#define NB      64
#define NSTEP   (P / NB)      // 8
#define NSLICE  3
#define DP      68
#define NCTA    13            // 13 x 11 active = 143 <= 148 SMs -> solo CTAs
#define REG     4352          // smem region stride (floats)

#define FT_SMEM_BYTES (4 * REG * 4)   // 69632 B

typedef unsigned long long ull;

// ---------------- f32x2 packed helpers (Blackwell sm_103a) -----------------
__device__ __forceinline__ ull ffma2(ull a, ull b, ull c) {
    ull d;
    asm("fma.rn.f32x2 %0, %1, %2, %3;" : "=l"(d) : "l"(a), "l"(b), "l"(c));
    return d;
}
__device__ __forceinline__ ull dup2(float x) {
    ull r; unsigned xb = __float_as_uint(x);
    asm("mov.b64 %0, {%1, %2};" : "=l"(r) : "r"(xb), "r"(xb));
    return r;
}
__device__ __forceinline__ ull pack2(float lo, float hi) {
    ull r;
    asm("mov.b64 %0, {%1, %2};" : "=l"(r) : "f"(lo), "f"(hi));
    return r;
}
__device__ __forceinline__ float2 unpk2(ull v) {
    float2 r;
    asm("mov.b64 {%0, %1}, %2;" : "=f"(r.x), "=f"(r.y) : "l"(v));
    return r;
}

// ---------------- device scratch -------------------------------------------
__device__ int    d_cnt[K_MAX];
__device__ int    d_kval;
__device__ int    d_idx[M_CAP];
__device__ int    d_bh[NCH_MAX][K_MAX];
__device__ int    d_boff[NCH_MAX][K_MAX];
__device__ int    d_cstart[K_MAX];
__device__ int    d_lbar;
__device__ int    d_done;
__device__ int    d_zflag[NM];
__device__ int    d_wflag[NM][NSTEP - 1];
__device__ int    d_tflag[NM][64];
__device__ float  d_Gk[NSLICE][K_MAX][P * P];
__device__ float  d_A[NM][P * P];
__device__ float  d_Z[NSTEP][NM][NB * 65];
__device__ float  d_W[NSTEP - 1][NM][NSTEP - 1][NB * DP];
__device__ double d_hldd[NM];

// ---------------- release/acquire primitives -------------------------------
__device__ __forceinline__ void rel_add(int* p) {
    int d;
    asm volatile("atom.release.gpu.add.s32 %0, [%1], 1;"
                 : "=r"(d) : "l"(p) : "memory");
}
__device__ __forceinline__ void rel_st(int* p, int v) {
    asm volatile("st.release.gpu.s32 [%0], %1;" :: "l"(p), "r"(v) : "memory");
}
__device__ __forceinline__ int acq_ld(const int* p) {
    int v;
    asm volatile("ld.acquire.gpu.s32 %0, [%1];" : "=r"(v) : "l"(p) : "memory");
    return v;
}
__device__ __forceinline__ void gbar(int nb, int ep) {
    __syncthreads();
    if (threadIdx.x == 0) {
        rel_add(&d_lbar);
        while (acq_ld(&d_lbar) < nb * ep) { }
    }
    __syncthreads();
}
__device__ __forceinline__ void fwait3(const int* p0, int v0,
                                       const int* p1, int v1,
                                       const int* p2, int v2) {
    if (threadIdx.x == 0) {
        if (p0) while (acq_ld(p0) < v0) { }
        if (p1) while (acq_ld(p1) < v1) { }
        if (p2) while (acq_ld(p2) < v2) { }
    }
    __syncthreads();
}

// ------- k_labels: dtype detect + hist + scan + stable scatter -------------
__global__ __launch_bounds__(256) void k_labels(const void* __restrict__ Y,
                                                const int* ncls, int m,
                                                int nchunk) {
    __shared__ int sh[K_MAX];
    __shared__ int swh[8 * K_MAX];
    __shared__ int nzf;
    int tid = threadIdx.x;
    int b = blockIdx.x;
    if (tid == 0) nzf = 0;
    if (tid < K_MAX) sh[tid] = 0;
    __syncthreads();

    int lim = m / 2; if (lim > 512) lim = 512;
    int found = 0;
    for (int i = tid; i < lim; i += 256)
        if (((const int*)Y)[2 * i + 1] != 0) found = 1;
    if (__any_sync(0xffffffffu, found)) {
        if ((tid & 31) == 0) atomicOr(&nzf, 1);
    }
    __syncthreads();
    int is64 = nzf ? 0 : 1;

    int i = b * 256 + tid;
    int c = -1;
    if (i < m) {
        c = is64 ? (int)((const long long*)Y)[i] : ((const int*)Y)[i];
        if (c < 0 || c >= K_MAX) c = 0;
        atomicAdd(&sh[c], 1);
    }
    __syncthreads();
    if (tid < K_MAX) d_bh[b][tid] = sh[tid];

    gbar(nchunk, 1);

    if (b == 0) {
        if (tid < K_MAX) {
            int run = 0;
            for (int bb = 0; bb < nchunk; bb++) {
                d_boff[bb][tid] = run;
                run += d_bh[bb][tid];
            }
            d_cnt[tid] = run;
            sh[tid] = run;
        }
        __syncthreads();
        if (tid == 0) {
            int run = 0;
            for (int cc = 0; cc < K_MAX; cc++) {
                d_cstart[cc] = run;
                run += sh[cc];
            }
            int k = ncls ? *ncls : 10;
            if (k < 1) k = 1;
            if (k > K_MAX) k = K_MAX;
            d_kval = k;
            d_done = 0;
        }
        if (tid < NM) { d_hldd[tid] = 0.0; d_zflag[tid] = 0; }
        for (int q = tid; q < NM * (NSTEP - 1); q += 256)
            ((int*)d_wflag)[q] = 0;
        for (int q = tid; q < NM * 64; q += 256)
            ((int*)d_tflag)[q] = 0;
    }

    gbar(nchunk, 2);

    if (tid < 8 * K_MAX) swh[tid] = 0;
    __syncthreads();
    int lane = tid & 31, w = tid >> 5;
    unsigned mask = __match_any_sync(0xffffffffu, c);
    int rin = __popc(mask & ((1u << lane) - 1u));
    int leader = __ffs(mask) - 1;
    if (c >= 0 && lane == leader) swh[w * K_MAX + c] = __popc(mask);
    __syncthreads();
    if (c >= 0) {
        int pre = 0;
        for (int w2 = 0; w2 < w; w2++) pre += swh[w2 * K_MAX + c];
        d_idx[d_cstart[c] + d_boff[b][c] + pre + rin] = i;
    }
}

// ------- per-class Gram: dense gather over sorted class range --------------
__global__ __launch_bounds__(256) void k_gram(const float* __restrict__ X,
                                              int p) {
    int c = blockIdx.y;
    if (c >= d_kval) return;
    int tile = blockIdx.x;
    int ti = 0;
    while ((ti + 1) * (ti + 2) / 2 <= tile) ti++;
    int tj = tile - ti * (ti + 1) / 2;
    int a0 = ti * 128, b0 = tj * 128;
    int z = blockIdx.z;
    int cstart = d_cstart[c], ccnt = d_cnt[c];
    int sb = (int)((long long)ccnt * z / NSLICE);
    int se = (int)((long long)ccnt * (z + 1) / NSLICE);

    __shared__ __align__(16) float sA[32][132];
    __shared__ __align__(16) float sB[32][132];
    __shared__ int sidx[32];

    int tid = threadIdx.x;
    int tx = tid & 15, ty = tid >> 4;
    int lt = tid >> 3, lc = tid & 7;

    ull acc2[8][4];
#pragma unroll
    for (int i = 0; i < 8; i++)
#pragma unroll
        for (int q = 0; q < 4; q++) acc2[i][q] = 0ull;

    for (int base = sb; base < se; base += 32) {
        int nv = se - base;
        if (nv > 32) nv = 32;
        __syncthreads();
        if (tid < 32)
            sidx[tid] = (tid < nv) ? d_idx[cstart + base + tid] : -1;
        __syncthreads();
        {
            int s = sidx[lt];
            if (s >= 0) {
                const float* xr = X + (size_t)s * p;
#pragma unroll
                for (int q = 0; q < 4; q++) {
                    int col = lc * 16 + q * 4;
                    *(float4*)&sA[lt][col] = *(const float4*)&xr[a0 + col];
                    *(float4*)&sB[lt][col] = *(const float4*)&xr[b0 + col];
                }
            }
        }
        __syncthreads();

        for (int t = 0; t < nv; t++) {
            float a[8];
            ull ad[8], b2[4];
            *(float4*)&a[0] = *(const float4*)&sA[t][ty * 8];
            *(float4*)&a[4] = *(const float4*)&sA[t][ty * 8 + 4];
#pragma unroll
            for (int i = 0; i < 8; i++) ad[i] = dup2(a[i]);
#pragma unroll
            for (int q = 0; q < 4; q++)
                b2[q] = *(const ull*)&sB[t][tx * 2 + q * 32];
#pragma unroll
            for (int i = 0; i < 8; i++)
#pragma unroll
                for (int q = 0; q < 4; q++)
                    acc2[i][q] = ffma2(ad[i], b2[q], acc2[i][q]);
        }
    }

    float* G = d_Gk[z][c];
    int gi = a0 + ty * 8;
#pragma unroll
    for (int i = 0; i < 8; i++)
#pragma unroll
        for (int q = 0; q < 4; q++) {
            float2 v = unpk2(acc2[i][q]);
            int col = b0 + q * 32 + tx * 2;
            *(float2*)&G[(size_t)(gi + i) * P + col] = v;
        }
    if (ti != tj) {
#pragma unroll
        for (int i = 0; i < 8; i++)
#pragma unroll
            for (int q = 0; q < 4; q++) {
                float2 v = unpk2(acc2[i][q]);
                int col = b0 + q * 32 + tx * 2;
                G[(size_t)col * P + gi + i]       = v.x;
                G[(size_t)(col + 1) * P + gi + i] = v.y;
            }
    }
}

// --------- assemble ---------------------------------------------------------
__global__ __launch_bounds__(256) void k_assemble(int m, float pf) {
    int idx4 = blockIdx.x * blockDim.x + threadIdx.x;
    if (idx4 >= P * P / 4) return;
    int idx = idx4 * 4;
    int r = idx >> 9, c0 = idx & 511;
    int kv = d_kval;
    float dg[4];
#pragma unroll
    for (int q = 0; q < 4; q++) dg[q] = (r == c0 + q) ? 1.f : 0.f;
    float sum[4] = {0.f, 0.f, 0.f, 0.f};
    for (int j = 0; j < kv; j++) {
        float4 g0 = *(const float4*)&d_Gk[0][j][idx];
        float4 g1 = *(const float4*)&d_Gk[1][j][idx];
        float4 g2 = *(const float4*)&d_Gk[2][j][idx];
        float g[4];
        g[0] = g0.x + g1.x + g2.x; g[1] = g0.y + g1.y + g2.y;
        g[2] = g0.z + g1.z + g2.z; g[3] = g0.w + g1.w + g2.w;
        float scal = pf / (((float)d_cnt[j] + 1e-8f) * 0.01f);
        float4 o;
        o.x = dg[0] + scal * g[0]; o.y = dg[1] + scal * g[1];
        o.z = dg[2] + scal * g[2]; o.w = dg[3] + scal * g[3];
        *(float4*)&d_A[j][idx] = o;
#pragma unroll
        for (int q = 0; q < 4; q++) sum[q] += g[q];
    }
    float scalar = pf / ((float)m * 0.01f);
    float4 o;
    o.x = dg[0] + scalar * sum[0]; o.y = dg[1] + scalar * sum[1];
    o.z = dg[2] + scalar * sum[2]; o.w = dg[3] + scalar * sum[3];
    *(float4*)&d_A[kv][idx] = o;
}

// ---- diag core: factor 64x64, logdet, Z=L^-1 ------------------------------
__device__ void diag_core(int mb, int sidx, int tid, float* sD, float* sZ,
                          float* scr) {
    float* sdinv = scr;
    float* sRed  = scr + 64;
    float* sW8   = scr + 128;
    bool needZ = (sidx < NSTEP - 1);
    if (needZ)
        for (int l = tid; l < NB * 65; l += 256) sZ[l] = 0.f;
    __syncthreads();

#pragma unroll 1
    for (int b = 0; b < NB; b += 8) {
        if (tid == 0) {
            float a[8][8];
#pragma unroll
            for (int i = 0; i < 8; i++)
#pragma unroll
                for (int u = 0; u <= i; u++)
                    a[i][u] = sD[(b + i) * 65 + b + u];
#pragma unroll
            for (int t = 0; t < 8; t++) {
                float rinv = rsqrtf(a[t][t]);
                a[t][t] *= rinv;
                sdinv[b + t] = rinv;
#pragma unroll
                for (int i = t + 1; i < 8; i++) a[i][t] *= rinv;
#pragma unroll
                for (int u = t + 1; u < 8; u++)
#pragma unroll
                    for (int i = u; i < 8; i++)
                        a[i][u] = fmaf(-a[i][t], a[u][t], a[i][u]);
            }
#pragma unroll
            for (int i = 0; i < 8; i++)
#pragma unroll
                for (int u = 0; u <= i; u++)
                    sD[(b + i) * 65 + b + u] = a[i][u];
        }
        __syncthreads();

        int rows = NB - b - 8;
        if (rows > 0) {
            if (tid < rows) {
                int r = b + 8 + tid;
                float x[8];
#pragma unroll
                for (int t = 0; t < 8; t++) x[t] = sD[r * 65 + b + t];
#pragma unroll
                for (int t = 0; t < 8; t++) {
                    float v = x[t];
#pragma unroll
                    for (int u = 0; u < t; u++)
                        v = fmaf(-x[u], sD[(b + t) * 65 + b + u], v);
                    x[t] = v * sdinv[b + t];
                }
#pragma unroll
                for (int t = 0; t < 8; t++) sD[r * 65 + b + t] = x[t];
            }
            __syncthreads();

            int total = rows << 6;
            for (int l = tid; l < total; l += 256) {
                int i = b + 8 + (l >> 6), u = l & 63;
                if (u >= b + 8 && u <= i) {
                    float acc = sD[i * 65 + u];
#pragma unroll
                    for (int t = 0; t < 8; t++)
                        acc = fmaf(-sD[i * 65 + b + t], sD[u * 65 + b + t],
                                   acc);
                    sD[i * 65 + u] = acc;
                }
            }
        }
        __syncthreads();
    }

    if (tid < NB) sRed[tid] = logf(sD[tid * 65 + tid]);
    __syncthreads();
    if (tid < 32) {
        double lsum = (double)sRed[tid] + (double)sRed[tid + 32];
#pragma unroll
        for (int o = 16; o > 0; o >>= 1)
            lsum += __shfl_down_sync(0xffffffffu, lsum, o);
        if (tid == 0) d_hldd[mb] += lsum;
    }
    if (!needZ) return;

    for (int b = 0; b < NB; b += 8) {
        {
            int t0 = tid >> 6;
            int j = tid & 63;
#pragma unroll
            for (int pass = 0; pass < 2; pass++) {
                int t = t0 + pass * 4;
                float acc = 0.f;
                for (int u = 0; u < b; u++)
                    acc = fmaf(sD[(b + t) * 65 + u], sZ[u * 65 + j], acc);
                sW8[t * 64 + j] = acc;
            }
        }
        __syncthreads();
        if (tid < 64) {
            int j = tid;
#pragma unroll
            for (int t = 0; t < 8; t++) {
                int r = b + t;
                if (j <= r) {
                    float v = ((r == j) ? 1.f : 0.f) - sW8[t * 64 + j];
#pragma unroll
                    for (int u = 0; u < 8; u++) {
                        if (u < t)
                            v = fmaf(-sD[r * 65 + b + u], sZ[(b + u) * 65 + j],
                                     v);
                    }
                    sZ[r * 65 + j] = v * sdinv[r];
                }
            }
        }
        __syncthreads();
    }
}

// ---- W GEMM: sWout[t][c] = sum_u Z[t][u] * AT[u][c] -----------------------
__device__ __forceinline__ void w_gemm(const float* sZ, const float* sAT,
                                       float* sWout, int tx, int ty) {
    ull acc2[4][2];
#pragma unroll
    for (int i = 0; i < 4; i++) { acc2[i][0] = 0ull; acc2[i][1] = 0ull; }
#pragma unroll 8
    for (int u = 0; u < NB; u++) {
        float4 bv = *(const float4*)&sAT[u * DP + tx * 4];
        ull b0 = pack2(bv.x, bv.y), b1 = pack2(bv.z, bv.w);
        ull a0 = dup2(sZ[(ty * 4 + 0) * 65 + u]);
        ull a1 = dup2(sZ[(ty * 4 + 1) * 65 + u]);
        ull a2 = dup2(sZ[(ty * 4 + 2) * 65 + u]);
        ull a3 = dup2(sZ[(ty * 4 + 3) * 65 + u]);
        acc2[0][0] = ffma2(a0, b0, acc2[0][0]);
        acc2[0][1] = ffma2(a0, b1, acc2[0][1]);
        acc2[1][0] = ffma2(a1, b0, acc2[1][0]);
        acc2[1][1] = ffma2(a1, b1, acc2[1][1]);
        acc2[2][0] = ffma2(a2, b0, acc2[2][0]);
        acc2[2][1] = ffma2(a2, b1, acc2[2][1]);
        acc2[3][0] = ffma2(a3, b0, acc2[3][0]);
        acc2[3][1] = ffma2(a3, b1, acc2[3][1]);
    }
#pragma unroll
    for (int q = 0; q < 4; q++) {
        float2 lo = unpk2(acc2[q][0]), hi = unpk2(acc2[q][1]);
        float4 v; v.x = lo.x; v.y = lo.y; v.z = hi.x; v.w = hi.y;
        *(float4*)&sWout[(ty * 4 + q) * DP + tx * 4] = v;
    }
}

__device__ __forceinline__ void at_load(const float* A, int r0, int sc,
                                        float* sAT, int tid) {
    int j = tid >> 2, u0 = (tid & 3) * 16;
    const float* row = &A[(size_t)(r0 + j) * P + sc];
#pragma unroll
    for (int q4 = 0; q4 < 4; q4++) {
        float4 v = *(const float4*)&row[u0 + q4 * 4];
        int u = u0 + q4 * 4;
        sAT[(u + 0) * DP + j] = v.x;
        sAT[(u + 1) * DP + j] = v.y;
        sAT[(u + 2) * DP + j] = v.z;
        sAT[(u + 3) * DP + j] = v.w;
    }
}

__device__ __forceinline__ void tile_gemm(const float* sWi, const float* sWj,
                                          int tx, int ty, ull acc2[4][2]) {
#pragma unroll
    for (int i = 0; i < 4; i++) { acc2[i][0] = 0ull; acc2[i][1] = 0ull; }
#pragma unroll 8
    for (int t = 0; t < NB; t++) {
        float4 av = *(const float4*)&sWi[t * DP + ty * 4];
        float4 bv = *(const float4*)&sWj[t * DP + tx * 4];
        ull b0 = pack2(bv.x, bv.y), b1 = pack2(bv.z, bv.w);
        ull a0 = dup2(av.x), a1 = dup2(av.y);
        ull a2 = dup2(av.z), a3 = dup2(av.w);
        acc2[0][0] = ffma2(a0, b0, acc2[0][0]);
        acc2[0][1] = ffma2(a0, b1, acc2[0][1]);
        acc2[1][0] = ffma2(a1, b0, acc2[1][0]);
        acc2[1][1] = ffma2(a1, b1, acc2[1][1]);
        acc2[2][0] = ffma2(a2, b0, acc2[2][0]);
        acc2[2][1] = ffma2(a2, b1, acc2[2][1]);
        acc2[3][0] = ffma2(a3, b0, acc2[3][0]);
        acc2[3][1] = ffma2(a3, b1, acc2[3][1]);
    }
}

// RMW a 64x64 tile of A with -acc
__device__ __forceinline__ void tile_rmw(float* A, int ri, int rj, int tx,
                                         int ty, ull acc2[4][2]) {
#pragma unroll
    for (int q = 0; q < 4; q++) {
        float2 lo = unpk2(acc2[q][0]), hi = unpk2(acc2[q][1]);
        float* row = &A[(size_t)(ri + ty * 4 + q) * P + rj + tx * 4];
        float4 v = *(float4*)row;
        v.x -= lo.x; v.y -= lo.y; v.z -= hi.x; v.w -= hi.y;
        *(float4*)row = v;
    }
}

// ---- k_chol: persistent dataflow + lookahead, solo-SM residency -----------
__global__ __launch_bounds__(256) void k_chol(float* out, int m) {
    int cx = blockIdx.x;
    int mb = blockIdx.y;
    if (mb > d_kval) return;
    extern __shared__ float fs[];
    int tid = threadIdx.x;
    int tx = tid & 15, ty = tid >> 4;
    float* A = d_A[mb];

    float* sZ  = fs;
    float* sAT = fs + REG;
    float* sWi = fs + 2 * REG;
    float* sWj = fs + 3 * REG;
    int* tfl = d_tflag[mb];

    if (cx == 0) {
        // ---- CTA0: critical chain ----
        {
            float* sD = sAT;
            for (int l = tid; l < NB * NB; l += 256) {
                int r = l >> 6, c = l & 63;
                sD[r * 65 + c] = A[(size_t)r * P + c];
            }
            __syncthreads();
            diag_core(mb, 0, tid, sD, sZ, sWj);
            float* Zg = d_Z[0][mb];
            for (int q = tid; q < NB * 65 / 4; q += 256)
                *(float4*)&Zg[q * 4] = *(const float4*)&sZ[q * 4];
            __syncthreads();
            if (tid == 0) rel_st(&d_zflag[mb], 1);
        }
        for (int s = 0; s < NSTEP - 1; s++) {
            int sc = s * NB;
            fwait3(&tfl[(s + 1) * 8 + s], s, &tfl[(s + 1) * 8 + s + 1], s,
                   0, 0);
            at_load(A, sc + NB, sc, sAT, tid);
            __syncthreads();
            w_gemm(sZ, sAT, sWi, tx, ty);
            __syncthreads();
            ull acc2[4][2];
            tile_gemm(sWi, sWi, tx, ty, acc2);
            float* sD = sAT;
            int r0 = sc + NB;
#pragma unroll
            for (int q = 0; q < 4; q++) {
                float2 lo = unpk2(acc2[q][0]), hi = unpk2(acc2[q][1]);
                const float* row =
                    &A[(size_t)(r0 + ty * 4 + q) * P + r0 + tx * 4];
                float4 v = *(const float4*)row;
                int rr = ty * 4 + q, cc = tx * 4;
                sD[rr * 65 + cc + 0] = v.x - lo.x;
                sD[rr * 65 + cc + 1] = v.y - lo.y;
                sD[rr * 65 + cc + 2] = v.z - hi.x;
                sD[rr * 65 + cc + 3] = v.w - hi.y;
            }
            __syncthreads();
            diag_core(mb, s + 1, tid, sD, sZ, sWj);
            if (s + 1 < NSTEP - 1) {
                float* Zg = d_Z[s + 1][mb];
                for (int q = tid; q < NB * 65 / 4; q += 256)
                    *(float4*)&Zg[q * 4] = *(const float4*)&sZ[q * 4];
                __syncthreads();
                if (tid == 0) rel_st(&d_zflag[mb], s + 2);
            }
        }
        if (tid == 0) {
            rel_add(&d_done);
            if (mb == 0) {
                int kv = d_kval;
                while (acq_ld(&d_done) < kv + 1) { }
                double comp = 0.0;
                for (int j = 0; j < kv; j++) {
                    double trPi = (double)d_cnt[j] + 1e-8;
                    comp += d_hldd[j] * trPi / (double)m;
                }
                out[0] = (float)d_hldd[kv];
                out[1] = (float)comp;
                d_lbar = 0;
            }
        }
        return;
    }

    if (cx == 1) {
        // ---- lookahead CTA: tiles (1,0) and (1,1) with local W ----
        for (int s = 0; s < NSTEP - 1; s++) {
            int nblk = NSTEP - 1 - s;
            if (nblk < 2) break;
            int sc = s * NB;
            int I = s + 2;
            fwait3(&d_zflag[mb], s + 1, &tfl[I * 8 + s + 1], s,
                   &tfl[I * 8 + I], s);
            fwait3(&tfl[I * 8 + s], s, 0, 0, 0, 0);
            {
                const float* Zg = d_Z[s][mb];
                for (int q = tid; q < NB * 65 / 4; q += 256)
                    *(float4*)&sZ[q * 4] = *(const float4*)&Zg[q * 4];
            }
            at_load(A, sc + NB, sc, sAT, tid);
            __syncthreads();
            w_gemm(sZ, sAT, sWi, tx, ty);
            __syncthreads();
            at_load(A, sc + 2 * NB, sc, sAT, tid);
            __syncthreads();
            w_gemm(sZ, sAT, sWj, tx, ty);
            __syncthreads();
            {
                ull acc2[4][2];
                tile_gemm(sWj, sWi, tx, ty, acc2);
                tile_rmw(A, sc + 2 * NB, sc + NB, tx, ty, acc2);
                __syncthreads();
                if (tid == 0) rel_st(&tfl[I * 8 + s + 1], s + 1);
            }
            {
                ull acc2[4][2];
                tile_gemm(sWj, sWj, tx, ty, acc2);
                tile_rmw(A, sc + 2 * NB, sc + 2 * NB, tx, ty, acc2);
                __syncthreads();
                if (tid == 0) rel_st(&tfl[I * 8 + I], s + 1);
            }
        }
        return;
    }

    // ---- bulk workers (cx = 2..NCTA-1): shared-W producers + consumers ----
    for (int s = 0; s < NSTEP - 1; s++) {
        int nblk = NSTEP - 1 - s;
        int ntile = nblk * (nblk + 1) / 2;
        int sc = s * NB;

        if (nblk > 2) {
            for (int panel = cx - 2; panel < nblk; panel += NCTA - 2) {
                fwait3(&d_zflag[mb], s + 1,
                       &tfl[(s + 1 + panel) * 8 + s], s, 0, 0);
                {
                    const float* Zg = d_Z[s][mb];
                    for (int q = tid; q < NB * 65 / 4; q += 256)
                        *(float4*)&sZ[q * 4] = *(const float4*)&Zg[q * 4];
                }
                at_load(A, sc + NB + panel * NB, sc, sAT, tid);
                __syncthreads();
                w_gemm(sZ, sAT, sWi, tx, ty);
                __syncthreads();
                float* Wg = d_W[s][mb][panel];
                for (int q = tid; q < NB * DP / 4; q += 256)
                    *(float4*)&Wg[q * 4] = *(const float4*)&sWi[q * 4];
                __syncthreads();
                if (tid == 0) rel_st(&d_wflag[mb][panel], s + 1);
            }
        }

        for (int l = 3 + (cx - 2); l < ntile; l += NCTA - 2) {
            int ti = 0;
            while ((ti + 1) * (ti + 2) / 2 <= l) ti++;
            int tj = l - ti * (ti + 1) / 2;
            int ri = sc + NB + ti * NB, rj = sc + NB + tj * NB;
            int I = s + 1 + ti, J = s + 1 + tj;

            __syncthreads();
            fwait3(&d_wflag[mb][ti], s + 1,
                   (ti != tj) ? &d_wflag[mb][tj] : 0, s + 1,
                   &tfl[I * 8 + J], s);
            {
                const float* Wg = d_W[s][mb][ti];
                for (int q = tid; q < NB * DP / 4; q += 256)
                    *(float4*)&sWi[q * 4] = *(const float4*)&Wg[q * 4];
            }
            const float* pWj = sWi;
            if (ti != tj) {
                const float* Wg = d_W[s][mb][tj];
                for (int q = tid; q < NB * DP / 4; q += 256)
                    *(float4*)&sWj[q * 4] = *(const float4*)&Wg[q * 4];
                pWj = sWj;
            }
            __syncthreads();
            ull acc2[4][2];
            tile_gemm(sWi, pWj, tx, ty, acc2);
            tile_rmw(A, ri, rj, tx, ty, acc2);
            __syncthreads();
            if (tid == 0) rel_st(&tfl[I * 8 + J], s + 1);
        }
    }
}

// ---------------- launch ----------------------------------------------------
extern "C" void kernel_launch(void* const* d_in, const int* in_sizes, int n_in,
                              void* d_out, int out_size) {
    const float* X    = (const float*)d_in[0];
    const void*  Y    = d_in[1];
    const int*   ncls = (n_in >= 3) ? (const int*)d_in[2] : nullptr;
    int m = in_sizes[1];
    int p = in_sizes[0] / m;          // 512
    float* out = (float*)d_out;
    (void)out_size;
    int nchunk = (m + 255) / 256;

    cudaFuncSetAttribute(k_chol, cudaFuncAttributeMaxDynamicSharedMemorySize,
                         FT_SMEM_BYTES);

    k_labels<<<nchunk, 256>>>(Y, ncls, m, nchunk);
    k_gram<<<dim3(10, K_MAX, NSLICE), 256>>>(X, p);
    k_assemble<<<(P * P / 4 + 255) / 256, 256>>>(m, (float)p);
    k_chol<<<dim3(NCTA, NM), 256, FT_SMEM_BYTES>>>(out, m);
}